// round 7
// baseline (speedup 1.0000x reference)
#include <cuda_runtime.h>
#include <cuda_bf16.h>

// Net_33294586479043 — TERMINAL KERNEL (confirmed stable over 3 identical
// benches: totals 4.58/4.86/4.86us, kernel 3.39/3.68/3.36us, rel_err 0.0).
//
// The network is a 2-layer GCN whose final layer has out_features=1, followed
// by log_softmax(axis=1) over a [N, 1] tensor. log_softmax on a size-1 axis
// is identically 0.0f (stable form: 0 - log(exp(0)) = -log(1) = 0, exact in
// fp32). The entire graph convolution (both SpMMs over 1.6M edges) is dead
// code; the reference output is 100,000 exact zeros.
//
// Minimum work: zero-fill 400KB of d_out (harness poisons it to 0xAA).
// Measured design landscape (total us):
//   grid-stride 1xSTG.128/thread, 98x256 : 4.58-4.86  <- this source (best)
//   2 stores/thread, 49 blocks           : 5.47
//   straight-line 1 store/thread         : 5.22
//   graph memset node (cudaMemsetAsync)  : 6.88
// Decomposition: ~3.4us kernel launch-ramp floor (ncu: DRAM 0.0%, issue ~6%,
// occ 13% — nothing on-chip binds) + ~1.3us harness graph-replay overhead.
// 400KB of stores is ~50ns of DRAM time; no source-level lever acts below
// the launch floor. Held unchanged to protect the confirmed optimum.

__global__ void zero_out_kernel(float4* __restrict__ out4, int n4,
                                float* __restrict__ out_tail, int tail_start, int n) {
    int i = blockIdx.x * blockDim.x + threadIdx.x;
    const float4 z = make_float4(0.f, 0.f, 0.f, 0.f);
    // grid-stride over float4 body (single iteration at the launched grid)
    for (int idx = i; idx < n4; idx += gridDim.x * blockDim.x) {
        out4[idx] = z;
    }
    // defensive tail (0..3 elements); no-op for out_size % 4 == 0
    if (i == 0) {
        for (int t = tail_start; t < n; ++t) out_tail[t] = 0.0f;
    }
}

extern "C" void kernel_launch(void* const* d_in, const int* in_sizes, int n_in,
                              void* d_out, int out_size) {
    (void)d_in; (void)in_sizes; (void)n_in;
    float* out = (float*)d_out;
    int n = out_size;          // 100000 expected
    int n4 = n / 4;            // 25000 float4 stores
    int tail_start = n4 * 4;

    int threads = 256;
    int blocks = (n4 + threads - 1) / threads;   // 98 for n=100000
    if (blocks < 1) blocks = 1;

    zero_out_kernel<<<blocks, threads>>>((float4*)out, n4, out, tail_start, n);
}

// round 8
// speedup vs baseline: 1.1118x; 1.1118x over previous
#include <cuda_runtime.h>
#include <cuda_bf16.h>

// Net_33294586479043 — TERMINAL KERNEL.
// Confirmed over 4 identical benches: kernel dur {3.39, 3.68, 3.36, 3.39}us
// (pinned at the ~3.4us launch-ramp floor), totals {4.58, 4.86, 4.86, 5.41}us
// (variance is harness graph-replay jitter, outside the kernel), rel_err 0.0.
//
// The network is a 2-layer GCN whose final layer has out_features=1, followed
// by log_softmax(axis=1) over a [N, 1] tensor. log_softmax on a size-1 axis
// is identically 0.0f (stable form: 0 - log(exp(0)) = -log(1) = 0, exact in
// fp32). The entire graph convolution (both SpMMs over 1.6M edges) is dead
// code; the reference output is 100,000 exact zeros.
//
// Minimum work: zero-fill 400KB of d_out (harness poisons it to 0xAA).
// Measured design landscape (total us):
//   grid-stride 1xSTG.128/thread, 98x256 : 4.58-5.41  <- this source (best)
//   2 stores/thread, 49 blocks           : 5.47
//   straight-line 1 store/thread         : 5.22
//   graph memset node (cudaMemsetAsync)  : 6.88
// 400KB of stores is ~50ns of DRAM time (ncu: DRAM 0.0%, issue ~5%); no
// source-level lever acts below the launch floor. Held unchanged to protect
// the confirmed optimum.

__global__ void zero_out_kernel(float4* __restrict__ out4, int n4,
                                float* __restrict__ out_tail, int tail_start, int n) {
    int i = blockIdx.x * blockDim.x + threadIdx.x;
    const float4 z = make_float4(0.f, 0.f, 0.f, 0.f);
    // grid-stride over float4 body (single iteration at the launched grid)
    for (int idx = i; idx < n4; idx += gridDim.x * blockDim.x) {
        out4[idx] = z;
    }
    // defensive tail (0..3 elements); no-op for out_size % 4 == 0
    if (i == 0) {
        for (int t = tail_start; t < n; ++t) out_tail[t] = 0.0f;
    }
}

extern "C" void kernel_launch(void* const* d_in, const int* in_sizes, int n_in,
                              void* d_out, int out_size) {
    (void)d_in; (void)in_sizes; (void)n_in;
    float* out = (float*)d_out;
    int n = out_size;          // 100000 expected
    int n4 = n / 4;            // 25000 float4 stores
    int tail_start = n4 * 4;

    int threads = 256;
    int blocks = (n4 + threads - 1) / threads;   // 98 for n=100000
    if (blocks < 1) blocks = 1;

    zero_out_kernel<<<blocks, threads>>>((float4*)out, n4, out, tail_start, n);
}

// round 9
// speedup vs baseline: 1.1818x; 1.0629x over previous
#include <cuda_runtime.h>
#include <cuda_bf16.h>

// Net_33294586479043 — TERMINAL KERNEL.
// Confirmed over 5 identical benches: kernel dur {3.39, 3.68, 3.36, 3.39,
// 3.81}us (launch-ramp floor ~3.4us; on-chip idle), totals {4.58, 4.86,
// 4.86, 5.41, 4.86}us (mode 4.86; variance is harness graph-replay jitter,
// independent of kernel dur), rel_err 0.0 every run.
//
// The network is a 2-layer GCN whose final layer has out_features=1,
// followed by log_softmax(axis=1) over a [N, 1] tensor. log_softmax on a
// size-1 axis is identically 0.0f (0 - log(exp(0)) = 0, exact in fp32).
// The entire graph convolution (both SpMMs over 1.6M edges) is dead code;
// the reference output is 100,000 exact zeros.
//
// Minimum work: zero-fill 400KB of d_out (harness poisons it to 0xAA).
// Closed-out design space (total us):
//   grid-stride 1xSTG.128/thread, 98x256 : 4.58-5.41  <- this source (best)
//   2 stores/thread, 49 blocks           : 5.47
//   straight-line 1 store/thread         : 5.22
//   graph memset node (cudaMemsetAsync)  : 6.88
//   single-CTA variant                   : rejected by model (~50us, 1 SM LSU-bound)
// 400KB of stores = ~50ns DRAM time (ncu: DRAM 0.0%, issue ~5-7%). No
// source-level lever exists below the launch floor; held to protect the
// confirmed optimum.

__global__ void zero_out_kernel(float4* __restrict__ out4, int n4,
                                float* __restrict__ out_tail, int tail_start, int n) {
    int i = blockIdx.x * blockDim.x + threadIdx.x;
    const float4 z = make_float4(0.f, 0.f, 0.f, 0.f);
    // grid-stride over float4 body (single iteration at the launched grid)
    for (int idx = i; idx < n4; idx += gridDim.x * blockDim.x) {
        out4[idx] = z;
    }
    // defensive tail (0..3 elements); no-op for out_size % 4 == 0
    if (i == 0) {
        for (int t = tail_start; t < n; ++t) out_tail[t] = 0.0f;
    }
}

extern "C" void kernel_launch(void* const* d_in, const int* in_sizes, int n_in,
                              void* d_out, int out_size) {
    (void)d_in; (void)in_sizes; (void)n_in;
    float* out = (float*)d_out;
    int n = out_size;          // 100000 expected
    int n4 = n / 4;            // 25000 float4 stores
    int tail_start = n4 * 4;

    int threads = 256;
    int blocks = (n4 + threads - 1) / threads;   // 98 for n=100000
    if (blocks < 1) blocks = 1;

    zero_out_kernel<<<blocks, threads>>>((float4*)out, n4, out, tail_start, n);
}